// round 9
// baseline (speedup 1.0000x reference)
#include <cuda_runtime.h>
#include <cuda_fp16.h>
#include <cstdint>

// LSTM single step, B=64, H=I=O=2048.  out[64,6144] = concat(y, h_new, c_new).
// mma.sync fp16 (fp16 accumulate, dumped to fp32 every K=32).
// CTA tile 64(M) x 128(N), warp tile 32x32 (8 warps = 2M x 4N) to cut
// shared-memory traffic per MMA.  288 CTAs x 16 k64-chunks, 2 CTAs/SM.

#define KD 2048
#define NOUT 6144

__device__ __half g_A[64 * 4096];            // concat(h, x) fp16
__device__ float g_part[4][4 * 64 * KD];     // gate partials, 4 K-slices
__device__ float g_yp[2][64 * KD];           // y partials, 2 K-slices

#define SWZ128(o) ((o) ^ (((o) >> 3) & 0x70))

__device__ __forceinline__ uint32_t smem_u32(const void* p) {
    uint32_t a;
    asm("{ .reg .u64 t; cvta.to.shared.u64 t, %1; cvt.u32.u64 %0, t; }"
        : "=r"(a) : "l"(p));
    return a;
}

#define LDSM4(r, addr)                                                       \
    asm volatile("ldmatrix.sync.aligned.m8n8.x4.shared.b16 {%0,%1,%2,%3}, [%4];" \
                 : "=r"((r)[0]), "=r"((r)[1]), "=r"((r)[2]), "=r"((r)[3])    \
                 : "r"(addr))
#define LDSM4T(r, addr)                                                      \
    asm volatile("ldmatrix.sync.aligned.m8n8.x4.trans.shared.b16 {%0,%1,%2,%3}, [%4];" \
                 : "=r"((r)[0]), "=r"((r)[1]), "=r"((r)[2]), "=r"((r)[3])    \
                 : "r"(addr))
#define MMA16816H(d, a, b0, b1)                                              \
    asm volatile("mma.sync.aligned.m16n8k16.row.col.f16.f16.f16.f16 "        \
                 "{%0,%1}, {%2,%3,%4,%5}, {%6,%7}, {%0,%1};"                 \
                 : "+r"((d)[0]), "+r"((d)[1])                                \
                 : "r"((a)[0]), "r"((a)[1]), "r"((a)[2]), "r"((a)[3]),       \
                   "r"(b0), "r"(b1))
#define CP_ASYNC16(saddr, gptr)                                              \
    asm volatile("cp.async.cg.shared.global [%0], [%1], 16;" :: "r"(saddr), "l"(gptr))
#define CP_COMMIT() asm volatile("cp.async.commit_group;" ::: "memory")
#define CP_WAIT1()  asm volatile("cp.async.wait_group 1;" ::: "memory")

// SMEM (relative to 1KB-aligned base):
//   A stages (3): s*8192                   (64 rows x 128B fp16)
//   B stages (2): 24576 + s*16384          (two 8KB panels of 64 cols each)
#define A_OFF(s)  ((uint32_t)(s) * 8192u)
#define B_OFF(s)  (24576u + (uint32_t)(s) * 16384u)
#define SMEM_BYTES (57344 + 1024)

// ---------------------------------------------------------------------------
__global__ void make_A(const float* __restrict__ h, const float* __restrict__ x) {
    int u = blockIdx.x * 256 + threadIdx.x;     // 65536 units of 4 elems
    int idx = u * 4;
    int r = idx >> 12, k = idx & 4095;
    const float* src = (k < 2048) ? (h + r * 2048 + k) : (x + r * 2048 + (k - 2048));
    float4 v = *(const float4*)src;
    __half2 p0 = __floats2half2_rn(v.x, v.y);
    __half2 p1 = __floats2half2_rn(v.z, v.w);
    *(uint2*)(g_A + idx) = make_uint2(*(uint32_t*)&p0, *(uint32_t*)&p1);
}

// ---------------------------------------------------------------------------
// GEMM: 288 CTAs x 16 K-chunks (k64).
//  bx in [0,256): tile=bx>>2 (g=tile>>4, jj=(tile&15)*128), kk=bx&3.
//      W = (kk>=2) ? Wgx : Wgh, rows (kk&1)*1024; A cols kk*1024.
//      Partial -> g_part[kk].
//  bx in [256,288): u=bx-256: jj=(u>>1)*128, kk=u&1; W=Wy rows kk*1024,
//      A cols kk*1024. Partial -> g_yp[kk].
// 8 warps: mi=w&1 (32 rows), ni=w>>1 (32 cols).
// ---------------------------------------------------------------------------
__global__ void __launch_bounds__(256, 2) gemm_hmma(
    const float* __restrict__ Wfh, const float* __restrict__ Wfx,
    const float* __restrict__ Wih, const float* __restrict__ Wix,
    const float* __restrict__ Wch, const float* __restrict__ Wcx,
    const float* __restrict__ Woh, const float* __restrict__ Wox,
    const float* __restrict__ Wy)
{
    extern __shared__ char smem_raw[];
    uint32_t su0 = smem_u32(smem_raw);
    const uint32_t su = (su0 + 1023u) & ~1023u;
    char* sm = smem_raw + (su - su0);

    const int t = threadIdx.x, bx = blockIdx.x;
    const int lane = t & 31, wid = t >> 5;
    const int mi = wid & 1, ni = wid >> 1;
    const int lr = lane & 15, lc = lane >> 4;

    const float* WH[4] = {Wfh, Wih, Wch, Woh};
    const float* WX[4] = {Wfx, Wix, Wcx, Wox};

    const float* W;
    float* Cout;
    int jj, aCol0, wRow0;
    if (bx < 256) {
        const int tile = bx >> 2, kk = bx & 3;
        const int g = tile >> 4;
        jj = (tile & 15) * 128;
        W = (kk >> 1) ? WX[g] : WH[g];
        wRow0 = (kk & 1) * 1024;
        aCol0 = kk * 1024;
        Cout = g_part[kk] + g * 64 * KD + jj;
    } else {
        const int u = bx - 256, kk = u & 1;
        jj = (u >> 1) * 128;
        W = Wy;
        wRow0 = kk * 1024;
        aCol0 = kk * 1024;
        Cout = g_yp[kk] + jj;
    }

    // B staging role: thread -> (row = t>>2, cseg = t&3 covering 32 cols).
    const int brow = t >> 2, cseg = t & 3;
    const int bpanel = cseg >> 1;                       // 0: cols 0-63, 1: 64-127
    const uint32_t brbse = brow * 128 + (cseg & 1) * 64;

    float master[2][4][4];
    uint32_t acch[2][4][2];
#pragma unroll
    for (int mf = 0; mf < 2; mf++)
#pragma unroll
        for (int j = 0; j < 4; j++) {
#pragma unroll
            for (int q = 0; q < 4; q++) master[mf][j][q] = 0.f;
            acch[mf][j][0] = 0u; acch[mf][j][1] = 0u;
        }

    auto issueA = [&](int c, int s) {
        const int aK = aCol0 + c * 64;
#pragma unroll
        for (int ui = 0; ui < 2; ui++) {
            const int u = t * 2 + ui;
            const int row = u >> 3, cs = u & 7;
            const uint32_t saddr = su + A_OFF(s) + SWZ128(row * 128 + cs * 16);
            const __half* gsrc = g_A + (size_t)row * 4096 + aK + cs * 8;
            CP_ASYNC16(saddr, gsrc);
        }
    };
    auto ldgB = [&](int c, float4* rb) {
        const float* src = W + (size_t)(wRow0 + c * 64 + brow) * 2048 + jj + cseg * 32;
#pragma unroll
        for (int q = 0; q < 8; q++) rb[q] = *(const float4*)(src + q * 4);
    };

    issueA(0, 0);
    CP_COMMIT();
    float4 rb[8];
    ldgB(0, rb);

    for (int c = 0; c < 16; ++c) {
        const int sa = c % 3, sb = c & 1;

        // Convert + STS B(c): 32 fp32 -> 16 half2, into panel bpanel.
        {
            uint32_t hp[16];
#pragma unroll
            for (int q = 0; q < 8; q++) {
                __half2 e0 = __floats2half2_rn(rb[q].x, rb[q].y);
                __half2 e1 = __floats2half2_rn(rb[q].z, rb[q].w);
                hp[q * 2]     = *(uint32_t*)&e0;
                hp[q * 2 + 1] = *(uint32_t*)&e1;
            }
            char* pb = sm + B_OFF(sb) + bpanel * 8192;
#pragma unroll
            for (int u2 = 0; u2 < 4; u2++)
                *(uint4*)(pb + SWZ128(brbse + u2 * 16)) =
                    make_uint4(hp[u2*4], hp[u2*4+1], hp[u2*4+2], hp[u2*4+3]);
        }

        if (c + 1 < 16) issueA(c + 1, (c + 1) % 3);
        CP_COMMIT();
        CP_WAIT1();           // A(c) resident
        __syncthreads();

        if (c + 1 < 16) ldgB(c + 1, rb);

        // Compute chunk c: per k16: 2 A frags + 2 B frags -> 8 MMAs.
        {
            const uint32_t aBase = su + A_OFF(sa);
            const uint32_t bBase = su + B_OFF(sb) + (ni >> 1) * 8192;
            const uint32_t nOff = (ni & 1) * 64;
#pragma unroll
            for (int ks = 0; ks < 4; ks++) {
                uint32_t a0[4], a1[4];
                LDSM4(a0, aBase + SWZ128((mi * 32 + lr) * 128 + ks * 32 + lc * 16));
                LDSM4(a1, aBase + SWZ128((mi * 32 + 16 + lr) * 128 + ks * 32 + lc * 16));
                const uint32_t brw = (ks * 16 + lr) * 128 + nOff;
                uint32_t b0[4], b1[4];
                LDSM4T(b0, bBase + SWZ128(brw + lc * 16));
                LDSM4T(b1, bBase + SWZ128(brw + 32 + lc * 16));
                MMA16816H(acch[0][0], a0, b0[0], b0[1]);
                MMA16816H(acch[0][1], a0, b0[2], b0[3]);
                MMA16816H(acch[0][2], a0, b1[0], b1[1]);
                MMA16816H(acch[0][3], a0, b1[2], b1[3]);
                MMA16816H(acch[1][0], a1, b0[0], b0[1]);
                MMA16816H(acch[1][1], a1, b0[2], b0[3]);
                MMA16816H(acch[1][2], a1, b1[0], b1[1]);
                MMA16816H(acch[1][3], a1, b1[2], b1[3]);
                if (ks & 1) {   // dump K=32 segment to fp32 masters
#pragma unroll
                    for (int mf = 0; mf < 2; mf++)
#pragma unroll
                        for (int j = 0; j < 4; j++) {
                            float2 lo = __half22float2(*(__half2*)&acch[mf][j][0]);
                            float2 hi = __half22float2(*(__half2*)&acch[mf][j][1]);
                            master[mf][j][0] += lo.x; master[mf][j][1] += lo.y;
                            master[mf][j][2] += hi.x; master[mf][j][3] += hi.y;
                            acch[mf][j][0] = 0u; acch[mf][j][1] = 0u;
                        }
                }
            }
        }
    }

    // Epilogue: warp writes 32 rows x 32 cols of raw partial.
    {
        const int c2 = (lane & 3) * 2;
#pragma unroll
        for (int mf = 0; mf < 2; mf++) {
            const int m0 = mi * 32 + mf * 16 + (lane >> 2);
#pragma unroll
            for (int j = 0; j < 4; j++) {
                const int n = ni * 32 + j * 8 + c2;
                *(float2*)(Cout + (size_t)m0 * KD + n) =
                    make_float2(master[mf][j][0], master[mf][j][1]);
                *(float2*)(Cout + (size_t)(m0 + 8) * KD + n) =
                    make_float2(master[mf][j][2], master[mf][j][3]);
            }
        }
    }
}

// ---------------------------------------------------------------------------
// Fuse: sum split-K partials + biases, LSTM pointwise, write y, h, c.
// ---------------------------------------------------------------------------
__global__ void fuse_kernel(const float* __restrict__ c_prev,
                            const float* __restrict__ bf_, const float* __restrict__ bi_,
                            const float* __restrict__ bc_, const float* __restrict__ bo_,
                            const float* __restrict__ by_,
                            float* __restrict__ out) {
    int idx = blockIdx.x * 256 + threadIdx.x;   // 64 * 2048
    int r = idx >> 11, j = idx & 2047;
    float gf = bf_[j], gi = bi_[j], gc = bc_[j], go = bo_[j];
#pragma unroll
    for (int s = 0; s < 4; s++) {
        gf += g_part[s][0 * 64 * KD + idx];
        gi += g_part[s][1 * 64 * KD + idx];
        gc += g_part[s][2 * 64 * KD + idx];
        go += g_part[s][3 * 64 * KD + idx];
    }
    float y = g_yp[0][idx] + g_yp[1][idx] + by_[j];
    float f  = 1.f / (1.f + expf(-gf));
    float ii = 1.f / (1.f + expf(-gi));
    float ct = tanhf(gc);
    float o  = 1.f / (1.f + expf(-go));
    float c  = f * c_prev[idx] + ii * ct;
    float h  = o * tanhf(c);
    out[r * NOUT + j] = y;
    out[r * NOUT + 2048 + j] = h;
    out[r * NOUT + 4096 + j] = c;
}

// ---------------------------------------------------------------------------
extern "C" void kernel_launch(void* const* d_in, const int* in_sizes, int n_in,
                              void* d_out, int out_size) {
    const float* x      = (const float*)d_in[0];
    const float* h_prev = (const float*)d_in[1];
    const float* c_prev = (const float*)d_in[2];
    const float* Wfh = (const float*)d_in[3];
    const float* Wfx = (const float*)d_in[4];
    const float* bf  = (const float*)d_in[5];
    const float* Wih = (const float*)d_in[6];
    const float* Wix = (const float*)d_in[7];
    const float* bi  = (const float*)d_in[8];
    const float* Woh = (const float*)d_in[9];
    const float* Wox = (const float*)d_in[10];
    const float* bo  = (const float*)d_in[11];
    const float* Wch = (const float*)d_in[12];
    const float* Wcx = (const float*)d_in[13];
    const float* bc  = (const float*)d_in[14];
    const float* Wy  = (const float*)d_in[15];
    const float* by  = (const float*)d_in[16];
    float* out = (float*)d_out;

    static int smem_set = 0;
    if (!smem_set) {
        cudaFuncSetAttribute(gemm_hmma, cudaFuncAttributeMaxDynamicSharedMemorySize,
                             SMEM_BYTES);
        smem_set = 1;
    }

    make_A<<<256, 256>>>(h_prev, x);
    gemm_hmma<<<288, 256, SMEM_BYTES>>>(Wfh, Wfx, Wih, Wix, Wch, Wcx, Woh, Wox, Wy);
    fuse_kernel<<<512, 256>>>(c_prev, bf, bi, bc, bo, by, out);
}

// round 10
// speedup vs baseline: 1.1973x; 1.1973x over previous
#include <cuda_runtime.h>
#include <cuda_fp16.h>
#include <cstdint>

// LSTM single step, B=64, H=I=O=2048.  out[64,6144] = concat(y, h_new, c_new).
// mma.sync fp16 (fp16 accumulate, dumped to fp32 every K=32).
// Split-K at h/x boundary: 256 gate CTAs + 32 y CTAs = 288 x 32 chunks,
// 2 CTAs/SM.  A is converted fp32->fp16 inside the GEMM (no prologue kernel).

#define KD 2048
#define NOUT 6144

__device__ float g_part[2][4 * 64 * KD];     // split-K gate partials

#define SWZ128(o) ((o) ^ (((o) >> 3) & 0x70))

__device__ __forceinline__ uint32_t smem_u32(const void* p) {
    uint32_t a;
    asm("{ .reg .u64 t; cvta.to.shared.u64 t, %1; cvt.u32.u64 %0, t; }"
        : "=r"(a) : "l"(p));
    return a;
}

#define LDSM4(r, addr)                                                       \
    asm volatile("ldmatrix.sync.aligned.m8n8.x4.shared.b16 {%0,%1,%2,%3}, [%4];" \
                 : "=r"((r)[0]), "=r"((r)[1]), "=r"((r)[2]), "=r"((r)[3])    \
                 : "r"(addr))
#define LDSM4T(r, addr)                                                      \
    asm volatile("ldmatrix.sync.aligned.m8n8.x4.trans.shared.b16 {%0,%1,%2,%3}, [%4];" \
                 : "=r"((r)[0]), "=r"((r)[1]), "=r"((r)[2]), "=r"((r)[3])    \
                 : "r"(addr))
#define MMA16816H(d, a, b0, b1)                                              \
    asm volatile("mma.sync.aligned.m16n8k16.row.col.f16.f16.f16.f16 "        \
                 "{%0,%1}, {%2,%3,%4,%5}, {%6,%7}, {%0,%1};"                 \
                 : "+r"((d)[0]), "+r"((d)[1])                                \
                 : "r"((a)[0]), "r"((a)[1]), "r"((a)[2]), "r"((a)[3]),       \
                   "r"(b0), "r"(b1))

// SMEM (relative to 1KB-aligned base):
//   A stages (2): s*8192            (64 rows x 128B fp16)
//   B stages (2): 16384 + s*8192
#define A_OFF(s)  ((uint32_t)(s) * 8192u)
#define B_OFF(s)  (16384u + (uint32_t)(s) * 8192u)
#define SMEM_BYTES (32768 + 1024)

// ---------------------------------------------------------------------------
// GEMM: 288 CTAs x 32 K-chunks (k64 each).
//  bx in [0,256): tile=bx>>1 (g=tile>>5, jj=(tile&31)*64), kk=bx&1.
//      W = kk ? Wgx : Wgh;  A source = kk ? x : h.  Partial -> g_part[kk].
//  bx in [256,288): y tile jj=(bx-256)*64, W=Wy, A=h, +bias -> out directly.
// CTA tile 64(M) x 64(N); 8 warps: mi=w&3 (16 rows), ni=w>>2 (32 cols).
// ---------------------------------------------------------------------------
__global__ void __launch_bounds__(256, 2) gemm_hmma(
    const float* __restrict__ h_prev, const float* __restrict__ x_in,
    const float* __restrict__ Wfh, const float* __restrict__ Wfx,
    const float* __restrict__ Wih, const float* __restrict__ Wix,
    const float* __restrict__ Wch, const float* __restrict__ Wcx,
    const float* __restrict__ Woh, const float* __restrict__ Wox,
    const float* __restrict__ Wy,  const float* __restrict__ by_,
    float* __restrict__ out)
{
    extern __shared__ char smem_raw[];
    uint32_t su0 = smem_u32(smem_raw);
    const uint32_t su = (su0 + 1023u) & ~1023u;
    char* sm = smem_raw + (su - su0);

    const int t = threadIdx.x, bx = blockIdx.x;
    const int lane = t & 31, wid = t >> 5;
    const int mi = wid & 3, ni = wid >> 2;
    const int lr = lane & 15, lc = lane >> 4;

    const float* WH[4] = {Wfh, Wih, Wch, Woh};
    const float* WX[4] = {Wfx, Wix, Wcx, Wox};

    const bool isY = (bx >= 256);
    const float *W, *Asrc, *bias = by_;
    float* Cout;
    int jj, ldc;
    if (!isY) {
        const int tile = bx >> 1, kk = bx & 1;
        const int g = tile >> 5;
        jj = (tile & 31) * 64;
        W = kk ? WX[g] : WH[g];
        Asrc = kk ? x_in : h_prev;
        Cout = g_part[kk] + g * 64 * KD + jj;
        ldc = KD;
    } else {
        jj = (bx - 256) * 64;
        W = Wy;
        Asrc = h_prev;
        Cout = out + jj;
        ldc = NOUT;
    }

    // Staging role (same map for A and B): row = t>>2 (64 rows), seg = t&3
    // (16 fp32 columns each).
    const int srow = t >> 2, sseg = t & 3;
    const uint32_t stsBase = srow * 128 + sseg * 32;     // bytes in fp16 tile

    float master[4][4];
    uint32_t acch[4][2];
#pragma unroll
    for (int j = 0; j < 4; j++) {
#pragma unroll
        for (int q = 0; q < 4; q++) master[j][q] = 0.f;
        acch[j][0] = 0u; acch[j][1] = 0u;
    }

    auto ldgA = [&](int c, float4* ra) {
        const float* src = Asrc + (size_t)srow * 2048 + c * 64 + sseg * 16;
#pragma unroll
        for (int q = 0; q < 4; q++) ra[q] = *(const float4*)(src + q * 4);
    };
    auto ldgB = [&](int c, float4* rb) {
        const float* src = W + (size_t)(c * 64 + srow) * 2048 + jj + sseg * 16;
#pragma unroll
        for (int q = 0; q < 4; q++) rb[q] = *(const float4*)(src + q * 4);
    };
    auto cvtSts = [&](const float4* r, char* dst) {
        uint32_t hp[8];
#pragma unroll
        for (int q = 0; q < 4; q++) {
            __half2 e0 = __floats2half2_rn(r[q].x, r[q].y);
            __half2 e1 = __floats2half2_rn(r[q].z, r[q].w);
            hp[q * 2]     = *(uint32_t*)&e0;
            hp[q * 2 + 1] = *(uint32_t*)&e1;
        }
        *(uint4*)(dst + SWZ128(stsBase))      = make_uint4(hp[0], hp[1], hp[2], hp[3]);
        *(uint4*)(dst + SWZ128(stsBase + 16)) = make_uint4(hp[4], hp[5], hp[6], hp[7]);
    };

    float4 ra[4], rb[4];
    ldgA(0, ra);
    ldgB(0, rb);

    for (int c = 0; c < 32; ++c) {
        const int s = c & 1;

        // Stage A(c), B(c) into buffers s (registers -> fp16 smem).
        cvtSts(ra, sm + A_OFF(s));
        cvtSts(rb, sm + B_OFF(s));

        // Prefetch next chunk BEFORE the barrier: maximum latency cover.
        if (c + 1 < 32) { ldgA(c + 1, ra); ldgB(c + 1, rb); }

        __syncthreads();

        // Compute chunk c: 16 fp16-accum MMAs / warp; dump to fp32 every 2 k16.
        {
            const uint32_t aBase = su + A_OFF(s);
            const uint32_t bBase = su + B_OFF(s);
#pragma unroll
            for (int ks = 0; ks < 4; ks++) {
                uint32_t a[4];
                LDSM4(a, aBase + SWZ128((mi * 16 + lr) * 128 + ks * 32 + lc * 16));
                const uint32_t brw = (ks * 16 + lr) * 128;
#pragma unroll
                for (int nc = 0; nc < 2; nc++) {
                    uint32_t b[4];
                    LDSM4T(b, bBase + SWZ128(brw + ni * 64 + nc * 32 + lc * 16));
                    MMA16816H(acch[nc*2+0], a, b[0], b[1]);
                    MMA16816H(acch[nc*2+1], a, b[2], b[3]);
                }
                if (ks & 1) {
#pragma unroll
                    for (int g2 = 0; g2 < 4; g2++) {
                        float2 lo = __half22float2(*(__half2*)&acch[g2][0]);
                        float2 hi = __half22float2(*(__half2*)&acch[g2][1]);
                        master[g2][0] += lo.x; master[g2][1] += lo.y;
                        master[g2][2] += hi.x; master[g2][3] += hi.y;
                        acch[g2][0] = 0u; acch[g2][1] = 0u;
                    }
                }
            }
        }
    }

    // Epilogue.
    {
        const int m0 = mi * 16 + (lane >> 2);
        const int c2 = (lane & 3) * 2;
#pragma unroll
        for (int j = 0; j < 4; j++) {
            const int n = ni * 32 + j * 8 + c2;
            float b0 = 0.f, b1 = 0.f;
            if (isY) { b0 = bias[jj + n]; b1 = bias[jj + n + 1]; }
            *(float2*)(Cout + (size_t)m0 * ldc + n) =
                make_float2(master[j][0] + b0, master[j][1] + b1);
            *(float2*)(Cout + (size_t)(m0 + 8) * ldc + n) =
                make_float2(master[j][2] + b0, master[j][3] + b1);
        }
    }
}

// ---------------------------------------------------------------------------
// Fuse: sum split-K partials + biases, LSTM pointwise, write h,c (float4).
// ---------------------------------------------------------------------------
__global__ void fuse_kernel(const float* __restrict__ c_prev,
                            const float* __restrict__ bf_, const float* __restrict__ bi_,
                            const float* __restrict__ bc_, const float* __restrict__ bo_,
                            float* __restrict__ out) {
    int u = blockIdx.x * 256 + threadIdx.x;     // 32768 units of 4
    int idx = u * 4;
    int r = idx >> 11, j = idx & 2047;
    float4 gf = *(const float4*)(&g_part[0][0 * 64 * KD + idx]);
    float4 gi = *(const float4*)(&g_part[0][1 * 64 * KD + idx]);
    float4 gc = *(const float4*)(&g_part[0][2 * 64 * KD + idx]);
    float4 go = *(const float4*)(&g_part[0][3 * 64 * KD + idx]);
    float4 t;
    t = *(const float4*)(&g_part[1][0 * 64 * KD + idx]);
    gf.x += t.x; gf.y += t.y; gf.z += t.z; gf.w += t.w;
    t = *(const float4*)(&g_part[1][1 * 64 * KD + idx]);
    gi.x += t.x; gi.y += t.y; gi.z += t.z; gi.w += t.w;
    t = *(const float4*)(&g_part[1][2 * 64 * KD + idx]);
    gc.x += t.x; gc.y += t.y; gc.z += t.z; gc.w += t.w;
    t = *(const float4*)(&g_part[1][3 * 64 * KD + idx]);
    go.x += t.x; go.y += t.y; go.z += t.z; go.w += t.w;
    float4 vbf = *(const float4*)(bf_ + j);
    float4 vbi = *(const float4*)(bi_ + j);
    float4 vbc = *(const float4*)(bc_ + j);
    float4 vbo = *(const float4*)(bo_ + j);
    float4 cp  = *(const float4*)(c_prev + idx);

    float hf[4], hc[4];
    float gfa[4] = {gf.x + vbf.x, gf.y + vbf.y, gf.z + vbf.z, gf.w + vbf.w};
    float gia[4] = {gi.x + vbi.x, gi.y + vbi.y, gi.z + vbi.z, gi.w + vbi.w};
    float gca[4] = {gc.x + vbc.x, gc.y + vbc.y, gc.z + vbc.z, gc.w + vbc.w};
    float goa[4] = {go.x + vbo.x, go.y + vbo.y, go.z + vbo.z, go.w + vbo.w};
    float cpa[4] = {cp.x, cp.y, cp.z, cp.w};
#pragma unroll
    for (int q = 0; q < 4; q++) {
        float f  = 1.f / (1.f + expf(-gfa[q]));
        float ii = 1.f / (1.f + expf(-gia[q]));
        float ct = tanhf(gca[q]);
        float o  = 1.f / (1.f + expf(-goa[q]));
        float cc = f * cpa[q] + ii * ct;
        hc[q] = cc;
        hf[q] = o * tanhf(cc);
    }
    *(float4*)(out + r * NOUT + 2048 + j) = make_float4(hf[0], hf[1], hf[2], hf[3]);
    *(float4*)(out + r * NOUT + 4096 + j) = make_float4(hc[0], hc[1], hc[2], hc[3]);
}

// ---------------------------------------------------------------------------
extern "C" void kernel_launch(void* const* d_in, const int* in_sizes, int n_in,
                              void* d_out, int out_size) {
    const float* x      = (const float*)d_in[0];
    const float* h_prev = (const float*)d_in[1];
    const float* c_prev = (const float*)d_in[2];
    const float* Wfh = (const float*)d_in[3];
    const float* Wfx = (const float*)d_in[4];
    const float* bf  = (const float*)d_in[5];
    const float* Wih = (const float*)d_in[6];
    const float* Wix = (const float*)d_in[7];
    const float* bi  = (const float*)d_in[8];
    const float* Woh = (const float*)d_in[9];
    const float* Wox = (const float*)d_in[10];
    const float* bo  = (const float*)d_in[11];
    const float* Wch = (const float*)d_in[12];
    const float* Wcx = (const float*)d_in[13];
    const float* bc  = (const float*)d_in[14];
    const float* Wy  = (const float*)d_in[15];
    const float* by  = (const float*)d_in[16];
    float* out = (float*)d_out;

    static int smem_set = 0;
    if (!smem_set) {
        cudaFuncSetAttribute(gemm_hmma, cudaFuncAttributeMaxDynamicSharedMemorySize,
                             SMEM_BYTES);
        smem_set = 1;
    }

    gemm_hmma<<<288, 256, SMEM_BYTES>>>(h_prev, x,
                                        Wfh, Wfx, Wih, Wix, Wch, Wcx, Woh, Wox,
                                        Wy, by, out);
    fuse_kernel<<<128, 256>>>(c_prev, bf, bi, bc, bo, out);
}

// round 11
// speedup vs baseline: 1.3864x; 1.1579x over previous
#include <cuda_runtime.h>
#include <cuda_fp16.h>
#include <cstdint>

// LSTM single step, B=64, H=I=O=2048.  out[64,6144] = concat(y, h_new, c_new).
// ONE persistent kernel, 288 CTAs (all co-resident at 2 CTAs/SM):
//   phase 0: convert concat(h,x) -> fp16 g_A            (cooperative)
//   phase 1: r7-proven HMMA GEMM (fp16 accum, fp32 dump every K=32)
//            256 gate CTAs (split-K at h/x) + 32 y CTAs, 32 k64-chunks each
//   phase 2: sum split-K partials + biases + LSTM pointwise -> h, c
// Grid barriers: monotone-ticket atomic counters (replay-safe, deterministic).

#define KD 2048
#define NOUT 6144
#define NCTA 288u

__device__ __half g_A[64 * 4096];            // concat(h, x) fp16
__device__ float g_part[2][4 * 64 * KD];     // split-K gate partials
__device__ unsigned g_tk0, g_tk1;            // barrier tickets (monotone)

#define SWZ128(o) ((o) ^ (((o) >> 3) & 0x70))

__device__ __forceinline__ uint32_t smem_u32(const void* p) {
    uint32_t a;
    asm("{ .reg .u64 t; cvta.to.shared.u64 t, %1; cvt.u32.u64 %0, t; }"
        : "=r"(a) : "l"(p));
    return a;
}

#define LDSM4(r, addr)                                                       \
    asm volatile("ldmatrix.sync.aligned.m8n8.x4.shared.b16 {%0,%1,%2,%3}, [%4];" \
                 : "=r"((r)[0]), "=r"((r)[1]), "=r"((r)[2]), "=r"((r)[3])    \
                 : "r"(addr))
#define LDSM4T(r, addr)                                                      \
    asm volatile("ldmatrix.sync.aligned.m8n8.x4.trans.shared.b16 {%0,%1,%2,%3}, [%4];" \
                 : "=r"((r)[0]), "=r"((r)[1]), "=r"((r)[2]), "=r"((r)[3])    \
                 : "r"(addr))
#define MMA16816H(d, a, b0, b1)                                              \
    asm volatile("mma.sync.aligned.m16n8k16.row.col.f16.f16.f16.f16 "        \
                 "{%0,%1}, {%2,%3,%4,%5}, {%6,%7}, {%0,%1};"                 \
                 : "+r"((d)[0]), "+r"((d)[1])                                \
                 : "r"((a)[0]), "r"((a)[1]), "r"((a)[2]), "r"((a)[3]),       \
                   "r"(b0), "r"(b1))
#define CP_ASYNC16(saddr, gptr)                                              \
    asm volatile("cp.async.cg.shared.global [%0], [%1], 16;" :: "r"(saddr), "l"(gptr))
#define CP_COMMIT() asm volatile("cp.async.commit_group;" ::: "memory")
#define CP_WAIT1()  asm volatile("cp.async.wait_group 1;" ::: "memory")

// SMEM (relative to 1KB-aligned base):
//   A stages (3): s*8192           (64 rows x 128B fp16)
//   B stages (2): 24576 + s*8192
#define A_OFF(s)  ((uint32_t)(s) * 8192u)
#define B_OFF(s)  (24576u + (uint32_t)(s) * 8192u)
#define SMEM_BYTES (40960 + 1024)

// Grid barrier: all 288 CTAs are co-resident (guaranteed by launch_bounds +
// smem: 288 <= 148 SMs * 2 CTAs/SM), so spinning is deadlock-free.  The
// monotone ticket makes it correct across graph replays with no reset.
__device__ __forceinline__ void grid_barrier(unsigned* ctr) {
    __threadfence();
    __syncthreads();
    if (threadIdx.x == 0) {
        unsigned my = atomicAdd(ctr, 1u);
        unsigned target = (my / NCTA + 1u) * NCTA;
        while (*(volatile unsigned*)ctr < target) __nanosleep(64);
    }
    __syncthreads();
    __threadfence();
}

// ---------------------------------------------------------------------------
__global__ void __launch_bounds__(256, 2) lstm_fused(
    const float* __restrict__ h_prev, const float* __restrict__ x_in,
    const float* __restrict__ c_prev,
    const float* __restrict__ Wfh, const float* __restrict__ Wfx,
    const float* __restrict__ Wih, const float* __restrict__ Wix,
    const float* __restrict__ Wch, const float* __restrict__ Wcx,
    const float* __restrict__ Woh, const float* __restrict__ Wox,
    const float* __restrict__ Wy,
    const float* __restrict__ bf_, const float* __restrict__ bi_,
    const float* __restrict__ bc_, const float* __restrict__ bo_,
    const float* __restrict__ by_,
    float* __restrict__ out)
{
    extern __shared__ char smem_raw[];
    uint32_t su0 = smem_u32(smem_raw);
    const uint32_t su = (su0 + 1023u) & ~1023u;
    char* sm = smem_raw + (su - su0);

    const int t = threadIdx.x, bx = blockIdx.x;
    const int lane = t & 31, wid = t >> 5;
    const int mi = wid & 3, ni = wid >> 2;
    const int lr = lane & 15, lc = lane >> 4;

    // ---------------- phase 0: build g_A (fp16 concat(h,x)) ----------------
    {
        int u = bx * 256 + t;                   // 73728 threads, 65536 units
        if (u < 65536) {
            int idx = u * 4;
            int r = idx >> 12, k = idx & 4095;
            const float* src = (k < 2048) ? (h_prev + r * 2048 + k)
                                          : (x_in + r * 2048 + (k - 2048));
            float4 v = *(const float4*)src;
            __half2 p0 = __floats2half2_rn(v.x, v.y);
            __half2 p1 = __floats2half2_rn(v.z, v.w);
            *(uint2*)(g_A + idx) = make_uint2(*(uint32_t*)&p0, *(uint32_t*)&p1);
        }
    }
    grid_barrier(&g_tk0);

    // ---------------- phase 1: GEMM (r7 structure, verbatim) ---------------
    const float* WH[4] = {Wfh, Wih, Wch, Woh};
    const float* WX[4] = {Wfx, Wix, Wcx, Wox};

    const bool isY = (bx >= 256);
    const float *W;
    float* Cout;
    int jj, ldc, aCol0;
    if (!isY) {
        const int tile = bx >> 1, kk = bx & 1;
        const int g = tile >> 5;
        jj = (tile & 31) * 64;
        W = kk ? WX[g] : WH[g];
        aCol0 = kk * 2048;
        Cout = g_part[kk] + g * 64 * KD + jj;
        ldc = KD;
    } else {
        jj = (bx - 256) * 64;
        W = Wy;
        aCol0 = 0;
        Cout = out + jj;
        ldc = NOUT;
    }

    const int brow = t >> 2, bseg = t & 3;      // B: 64 k-rows x 4 segs

    float master[4][4];
    uint32_t acch[4][2];
#pragma unroll
    for (int j = 0; j < 4; j++) {
#pragma unroll
        for (int q = 0; q < 4; q++) master[j][q] = 0.f;
        acch[j][0] = 0u; acch[j][1] = 0u;
    }

    auto issueA = [&](int c, int s) {
        const int aK = aCol0 + c * 64;
#pragma unroll
        for (int ui = 0; ui < 2; ui++) {
            const int u = t * 2 + ui;
            const int row = u >> 3, cs = u & 7;
            const uint32_t saddr = su + A_OFF(s) + SWZ128(row * 128 + cs * 16);
            const __half* gsrc = g_A + (size_t)row * 4096 + aK + cs * 8;
            CP_ASYNC16(saddr, gsrc);
        }
    };
    auto ldgB = [&](int c, float4* rb) {
        const float* src = W + (size_t)(c * 64 + brow) * 2048 + jj + bseg * 16;
        rb[0] = *(const float4*)(src + 0);
        rb[1] = *(const float4*)(src + 4);
        rb[2] = *(const float4*)(src + 8);
        rb[3] = *(const float4*)(src + 12);
    };

    issueA(0, 0);
    CP_COMMIT();
    float4 rb[4];
    ldgB(0, rb);

    for (int c = 0; c < 32; ++c) {
        const int s = c & 1;

        // Convert + STS B(c) fp32 -> fp16.
        {
            __half2 p[8];
            p[0] = __floats2half2_rn(rb[0].x, rb[0].y);
            p[1] = __floats2half2_rn(rb[0].z, rb[0].w);
            p[2] = __floats2half2_rn(rb[1].x, rb[1].y);
            p[3] = __floats2half2_rn(rb[1].z, rb[1].w);
            p[4] = __floats2half2_rn(rb[2].x, rb[2].y);
            p[5] = __floats2half2_rn(rb[2].z, rb[2].w);
            p[6] = __floats2half2_rn(rb[3].x, rb[3].y);
            p[7] = __floats2half2_rn(rb[3].z, rb[3].w);
            const uint32_t rbse = brow * 128 + bseg * 32;
            *(uint4*)(sm + B_OFF(s) + SWZ128(rbse)) =
                make_uint4(*(uint32_t*)&p[0], *(uint32_t*)&p[1],
                           *(uint32_t*)&p[2], *(uint32_t*)&p[3]);
            *(uint4*)(sm + B_OFF(s) + SWZ128(rbse + 16)) =
                make_uint4(*(uint32_t*)&p[4], *(uint32_t*)&p[5],
                           *(uint32_t*)&p[6], *(uint32_t*)&p[7]);
        }

        if (c + 1 < 32) issueA(c + 1, (c + 1) % 3);
        CP_COMMIT();
        CP_WAIT1();           // A(c) resident
        __syncthreads();

        if (c + 1 < 32) ldgB(c + 1, rb);

        // Compute chunk c: 16 fp16-accum MMAs / warp; dump to fp32 every 2 k16.
        {
            const int sa = c % 3;
            const uint32_t aBase = su + A_OFF(sa);
            const uint32_t bBase = su + B_OFF(s);
#pragma unroll
            for (int ks = 0; ks < 4; ks++) {
                uint32_t a[4];
                LDSM4(a, aBase + SWZ128((mi * 16 + lr) * 128 + ks * 32 + lc * 16));
                const uint32_t brw = (ks * 16 + lr) * 128;
#pragma unroll
                for (int nc = 0; nc < 2; nc++) {
                    uint32_t b[4];
                    LDSM4T(b, bBase + SWZ128(brw + ni * 64 + nc * 32 + lc * 16));
                    MMA16816H(acch[nc*2+0], a, b[0], b[1]);
                    MMA16816H(acch[nc*2+1], a, b[2], b[3]);
                }
                if (ks & 1) {
#pragma unroll
                    for (int g2 = 0; g2 < 4; g2++) {
                        float2 lo = __half22float2(*(__half2*)&acch[g2][0]);
                        float2 hi = __half22float2(*(__half2*)&acch[g2][1]);
                        master[g2][0] += lo.x; master[g2][1] += lo.y;
                        master[g2][2] += hi.x; master[g2][3] += hi.y;
                        acch[g2][0] = 0u; acch[g2][1] = 0u;
                    }
                }
            }
        }
    }

    // GEMM epilogue.
    {
        const int m0 = mi * 16 + (lane >> 2);
        const int c2 = (lane & 3) * 2;
#pragma unroll
        for (int j = 0; j < 4; j++) {
            const int n = ni * 32 + j * 8 + c2;
            float b0 = 0.f, b1 = 0.f;
            if (isY) { b0 = by_[jj + n]; b1 = by_[jj + n + 1]; }
            *(float2*)(Cout + (size_t)m0 * ldc + n) =
                make_float2(master[j][0] + b0, master[j][1] + b1);
            *(float2*)(Cout + (size_t)(m0 + 8) * ldc + n) =
                make_float2(master[j][2] + b0, master[j][3] + b1);
        }
    }

    grid_barrier(&g_tk1);

    // ---------------- phase 2: pointwise LSTM (partials are L2-hot) --------
    {
        const int base = bx * 512 + t;
#pragma unroll
        for (int e = 0; e < 2; e++) {
            const int idx = base + e * 256;
            if (idx < 64 * KD) {
                const int r = idx >> 11, j = idx & 2047;
                float gf = g_part[0][0 * 64 * KD + idx] + g_part[1][0 * 64 * KD + idx] + bf_[j];
                float gi = g_part[0][1 * 64 * KD + idx] + g_part[1][1 * 64 * KD + idx] + bi_[j];
                float gc = g_part[0][2 * 64 * KD + idx] + g_part[1][2 * 64 * KD + idx] + bc_[j];
                float go = g_part[0][3 * 64 * KD + idx] + g_part[1][3 * 64 * KD + idx] + bo_[j];
                float f  = 1.f / (1.f + expf(-gf));
                float ii = 1.f / (1.f + expf(-gi));
                float ct = tanhf(gc);
                float o  = 1.f / (1.f + expf(-go));
                float cc = f * c_prev[idx] + ii * ct;
                float hh = o * tanhf(cc);
                out[r * NOUT + 2048 + j] = hh;
                out[r * NOUT + 4096 + j] = cc;
            }
        }
    }
}

// ---------------------------------------------------------------------------
extern "C" void kernel_launch(void* const* d_in, const int* in_sizes, int n_in,
                              void* d_out, int out_size) {
    const float* x      = (const float*)d_in[0];
    const float* h_prev = (const float*)d_in[1];
    const float* c_prev = (const float*)d_in[2];
    const float* Wfh = (const float*)d_in[3];
    const float* Wfx = (const float*)d_in[4];
    const float* bf  = (const float*)d_in[5];
    const float* Wih = (const float*)d_in[6];
    const float* Wix = (const float*)d_in[7];
    const float* bi  = (const float*)d_in[8];
    const float* Woh = (const float*)d_in[9];
    const float* Wox = (const float*)d_in[10];
    const float* bo  = (const float*)d_in[11];
    const float* Wch = (const float*)d_in[12];
    const float* Wcx = (const float*)d_in[13];
    const float* bc  = (const float*)d_in[14];
    const float* Wy  = (const float*)d_in[15];
    const float* by  = (const float*)d_in[16];
    float* out = (float*)d_out;

    static int smem_set = 0;
    if (!smem_set) {
        cudaFuncSetAttribute(lstm_fused, cudaFuncAttributeMaxDynamicSharedMemorySize,
                             SMEM_BYTES);
        smem_set = 1;
    }

    lstm_fused<<<288, 256, SMEM_BYTES>>>(h_prev, x, c_prev,
                                         Wfh, Wfx, Wih, Wix, Wch, Wcx, Woh, Wox,
                                         Wy, bf, bi, bc, bo, by, out);
}

// round 12
// speedup vs baseline: 1.4936x; 1.0773x over previous
#include <cuda_runtime.h>
#include <cuda_fp16.h>
#include <cstdint>

// LSTM single step, B=64, H=I=O=2048.  out[64,6144] = concat(y, h_new, c_new).
// mma.sync fp16 (fp16 accum, fp32 dump once per k64 chunk; chain length 2).
// r7 skeleton: 256 gate CTAs (split-K at h/x) + 32 y CTAs = 288 x 32 chunks,
// 2 CTAs/SM.  NEW: warps split K inside the chunk -> 8 warps = 2M x 2N x 2K,
// warp tile 32x32: LDSM traffic per MMA drops 0.75 -> 0.5 (L1 was 63%, the
// top pipe; tensor only 15%).  K-halves recombined via smem at the end.

#define KD 2048
#define NOUT 6144

__device__ __half g_A[64 * 4096];            // concat(h, x) fp16
__device__ float g_part[2][4 * 64 * KD];     // split-K gate partials

#define SWZ128(o) ((o) ^ (((o) >> 3) & 0x70))

__device__ __forceinline__ uint32_t smem_u32(const void* p) {
    uint32_t a;
    asm("{ .reg .u64 t; cvta.to.shared.u64 t, %1; cvt.u32.u64 %0, t; }"
        : "=r"(a) : "l"(p));
    return a;
}

#define LDSM4(r, addr)                                                       \
    asm volatile("ldmatrix.sync.aligned.m8n8.x4.shared.b16 {%0,%1,%2,%3}, [%4];" \
                 : "=r"((r)[0]), "=r"((r)[1]), "=r"((r)[2]), "=r"((r)[3])    \
                 : "r"(addr))
#define LDSM4T(r, addr)                                                      \
    asm volatile("ldmatrix.sync.aligned.m8n8.x4.trans.shared.b16 {%0,%1,%2,%3}, [%4];" \
                 : "=r"((r)[0]), "=r"((r)[1]), "=r"((r)[2]), "=r"((r)[3])    \
                 : "r"(addr))
#define MMA16816H(d, a, b0, b1)                                              \
    asm volatile("mma.sync.aligned.m16n8k16.row.col.f16.f16.f16.f16 "        \
                 "{%0,%1}, {%2,%3,%4,%5}, {%6,%7}, {%0,%1};"                 \
                 : "+r"((d)[0]), "+r"((d)[1])                                \
                 : "r"((a)[0]), "r"((a)[1]), "r"((a)[2]), "r"((a)[3]),       \
                   "r"(b0), "r"(b1))
#define CP_ASYNC16(saddr, gptr)                                              \
    asm volatile("cp.async.cg.shared.global [%0], [%1], 16;" :: "r"(saddr), "l"(gptr))
#define CP_COMMIT() asm volatile("cp.async.commit_group;" ::: "memory")
#define CP_WAIT1()  asm volatile("cp.async.wait_group 1;" ::: "memory")

// SMEM (relative to 1KB-aligned base):
//   A stages (3): s*8192           (64 rows x 128B fp16)
//   B stages (2): 24576 + s*8192
#define A_OFF(s)  ((uint32_t)(s) * 8192u)
#define B_OFF(s)  (24576u + (uint32_t)(s) * 8192u)
#define SMEM_BYTES (40960 + 1024)

// ---------------------------------------------------------------------------
__global__ void make_A(const float* __restrict__ h, const float* __restrict__ x) {
    int u = blockIdx.x * 256 + threadIdx.x;     // 65536 units of 4 elems
    int idx = u * 4;
    int r = idx >> 12, k = idx & 4095;
    const float* src = (k < 2048) ? (h + r * 2048 + k) : (x + r * 2048 + (k - 2048));
    float4 v = *(const float4*)src;
    __half2 p0 = __floats2half2_rn(v.x, v.y);
    __half2 p1 = __floats2half2_rn(v.z, v.w);
    *(uint2*)(g_A + idx) = make_uint2(*(uint32_t*)&p0, *(uint32_t*)&p1);
}

// ---------------------------------------------------------------------------
// GEMM: 288 CTAs x 32 K-chunks (k64 each).
//  bx in [0,256): tile=bx>>1 (g=tile>>5, jj=(tile&31)*64), kk=bx&1.
//      W = kk ? Wgx : Wgh; A cols (kk*2048 ..). Partial -> g_part[kk].
//  bx in [256,288): y tile jj=(bx-256)*64, W=Wy, A = h half, bias, -> out.
// 8 warps: kh=w>>2 (k-half), mi=(w>>1)&1 (32 rows), ni=w&1 (32 cols).
// ---------------------------------------------------------------------------
__global__ void __launch_bounds__(256, 2) gemm_hmma(
    const float* __restrict__ Wfh, const float* __restrict__ Wfx,
    const float* __restrict__ Wih, const float* __restrict__ Wix,
    const float* __restrict__ Wch, const float* __restrict__ Wcx,
    const float* __restrict__ Woh, const float* __restrict__ Wox,
    const float* __restrict__ Wy,  const float* __restrict__ by_,
    float* __restrict__ out)
{
    extern __shared__ char smem_raw[];
    uint32_t su0 = smem_u32(smem_raw);
    const uint32_t su = (su0 + 1023u) & ~1023u;
    char* sm = smem_raw + (su - su0);

    const int t = threadIdx.x, bx = blockIdx.x;
    const int lane = t & 31, wid = t >> 5;
    const int kh = wid >> 2, mi = (wid >> 1) & 1, ni = wid & 1;
    const int lr = lane & 15, lc = lane >> 4;

    const float* WH[4] = {Wfh, Wih, Wch, Woh};
    const float* WX[4] = {Wfx, Wix, Wcx, Wox};

    const bool isY = (bx >= 256);
    const float *W;
    float* Cout;
    int jj, ldc, aCol0;
    if (!isY) {
        const int tile = bx >> 1, kk = bx & 1;
        const int g = tile >> 5;
        jj = (tile & 31) * 64;
        W = kk ? WX[g] : WH[g];
        aCol0 = kk * 2048;
        Cout = g_part[kk] + g * 64 * KD + jj;
        ldc = KD;
    } else {
        jj = (bx - 256) * 64;
        W = Wy;
        aCol0 = 0;
        Cout = out + jj;
        ldc = NOUT;
    }

    const int brow = t >> 2, bseg = t & 3;      // B staging: 64 k-rows x 4 segs

    float master[2][4][4];
    uint32_t acch[2][4][2];
#pragma unroll
    for (int mf = 0; mf < 2; mf++)
#pragma unroll
        for (int j = 0; j < 4; j++) {
#pragma unroll
            for (int q = 0; q < 4; q++) master[mf][j][q] = 0.f;
            acch[mf][j][0] = 0u; acch[mf][j][1] = 0u;
        }

    auto issueA = [&](int c, int s) {
        const int aK = aCol0 + c * 64;
#pragma unroll
        for (int ui = 0; ui < 2; ui++) {
            const int u = t * 2 + ui;
            const int row = u >> 3, cs = u & 7;
            const uint32_t saddr = su + A_OFF(s) + SWZ128(row * 128 + cs * 16);
            const __half* gsrc = g_A + (size_t)row * 4096 + aK + cs * 8;
            CP_ASYNC16(saddr, gsrc);
        }
    };
    auto ldgB = [&](int c, float4* rb) {
        const float* src = W + (size_t)(c * 64 + brow) * 2048 + jj + bseg * 16;
        rb[0] = *(const float4*)(src + 0);
        rb[1] = *(const float4*)(src + 4);
        rb[2] = *(const float4*)(src + 8);
        rb[3] = *(const float4*)(src + 12);
    };

    issueA(0, 0);
    CP_COMMIT();
    float4 rb[4];
    ldgB(0, rb);

    for (int c = 0; c < 32; ++c) {
        const int s = c & 1;

        // Convert + STS B(c) fp32 -> fp16.
        {
            __half2 p[8];
            p[0] = __floats2half2_rn(rb[0].x, rb[0].y);
            p[1] = __floats2half2_rn(rb[0].z, rb[0].w);
            p[2] = __floats2half2_rn(rb[1].x, rb[1].y);
            p[3] = __floats2half2_rn(rb[1].z, rb[1].w);
            p[4] = __floats2half2_rn(rb[2].x, rb[2].y);
            p[5] = __floats2half2_rn(rb[2].z, rb[2].w);
            p[6] = __floats2half2_rn(rb[3].x, rb[3].y);
            p[7] = __floats2half2_rn(rb[3].z, rb[3].w);
            const uint32_t rbse = brow * 128 + bseg * 32;
            *(uint4*)(sm + B_OFF(s) + SWZ128(rbse)) =
                make_uint4(*(uint32_t*)&p[0], *(uint32_t*)&p[1],
                           *(uint32_t*)&p[2], *(uint32_t*)&p[3]);
            *(uint4*)(sm + B_OFF(s) + SWZ128(rbse + 16)) =
                make_uint4(*(uint32_t*)&p[4], *(uint32_t*)&p[5],
                           *(uint32_t*)&p[6], *(uint32_t*)&p[7]);
        }

        if (c + 1 < 32) issueA(c + 1, (c + 1) % 3);
        CP_COMMIT();
        CP_WAIT1();           // A(c) resident
        __syncthreads();

        if (c + 1 < 32) ldgB(c + 1, rb);

        // Compute chunk c, this warp's k32 half: 2 ks steps x 8 MMAs.
        {
            const int sa = c % 3;
            const uint32_t aBase = su + A_OFF(sa);
            const uint32_t bBase = su + B_OFF(s);
#pragma unroll
            for (int ksl = 0; ksl < 2; ksl++) {
                const int ks = kh * 2 + ksl;
                uint32_t a0[4], a1[4];
                LDSM4(a0, aBase + SWZ128((mi * 32 + lr) * 128 + ks * 32 + lc * 16));
                LDSM4(a1, aBase + SWZ128((mi * 32 + 16 + lr) * 128 + ks * 32 + lc * 16));
                const uint32_t brw = (ks * 16 + lr) * 128 + ni * 64;
                uint32_t b0[4], b1[4];
                LDSM4T(b0, bBase + SWZ128(brw + lc * 16));
                LDSM4T(b1, bBase + SWZ128(brw + 32 + lc * 16));
                MMA16816H(acch[0][0], a0, b0[0], b0[1]);
                MMA16816H(acch[0][1], a0, b0[2], b0[3]);
                MMA16816H(acch[0][2], a0, b1[0], b1[1]);
                MMA16816H(acch[0][3], a0, b1[2], b1[3]);
                MMA16816H(acch[1][0], a1, b0[0], b0[1]);
                MMA16816H(acch[1][1], a1, b0[2], b0[3]);
                MMA16816H(acch[1][2], a1, b1[0], b1[1]);
                MMA16816H(acch[1][3], a1, b1[2], b1[3]);
            }
            // dump chunk (chain of 2) into fp32 masters, re-zero
#pragma unroll
            for (int mf = 0; mf < 2; mf++)
#pragma unroll
                for (int j = 0; j < 4; j++) {
                    float2 lo = __half22float2(*(__half2*)&acch[mf][j][0]);
                    float2 hi = __half22float2(*(__half2*)&acch[mf][j][1]);
                    master[mf][j][0] += lo.x; master[mf][j][1] += lo.y;
                    master[mf][j][2] += hi.x; master[mf][j][3] += hi.y;
                    acch[mf][j][0] = 0u; acch[mf][j][1] = 0u;
                }
        }
    }

    // Epilogue: combine the two k-halves via smem, then write.
    __syncthreads();                       // A/B buffers now free
    float* ex = (float*)sm;                // 4 tiles x 32x33 fp32 (16.9 KB)
    const int tl = mi * 2 + ni;
    if (kh == 1) {
#pragma unroll
        for (int mf = 0; mf < 2; mf++) {
            const int mb = mf * 16 + (lane >> 2);
#pragma unroll
            for (int j = 0; j < 4; j++) {
                const int nb = j * 8 + (lane & 3) * 2;
                float* p = ex + tl * 1056 + mb * 33 + nb;
                p[0]          = master[mf][j][0];
                p[1]          = master[mf][j][1];
                p[8 * 33]     = master[mf][j][2];
                p[8 * 33 + 1] = master[mf][j][3];
            }
        }
    }
    __syncthreads();
    if (kh == 0) {
#pragma unroll
        for (int mf = 0; mf < 2; mf++) {
            const int mb = mf * 16 + (lane >> 2);
            const int m0 = mi * 32 + mb;
#pragma unroll
            for (int j = 0; j < 4; j++) {
                const int nb = j * 8 + (lane & 3) * 2;
                const int n = ni * 32 + nb;
                const float* p = ex + tl * 1056 + mb * 33 + nb;
                float b0 = 0.f, b1 = 0.f;
                if (isY) { b0 = by_[jj + n]; b1 = by_[jj + n + 1]; }
                *(float2*)(Cout + (size_t)m0 * ldc + n) = make_float2(
                    master[mf][j][0] + p[0] + b0,
                    master[mf][j][1] + p[1] + b1);
                *(float2*)(Cout + (size_t)(m0 + 8) * ldc + n) = make_float2(
                    master[mf][j][2] + p[8 * 33] + b0,
                    master[mf][j][3] + p[8 * 33 + 1] + b1);
            }
        }
    }
}

// ---------------------------------------------------------------------------
// Fuse: sum split-K partials + biases, LSTM pointwise, write h,c.
// ---------------------------------------------------------------------------
__global__ void fuse_kernel(const float* __restrict__ c_prev,
                            const float* __restrict__ bf_, const float* __restrict__ bi_,
                            const float* __restrict__ bc_, const float* __restrict__ bo_,
                            float* __restrict__ out) {
    int idx = blockIdx.x * 256 + threadIdx.x;   // 64 * 2048
    int r = idx >> 11, j = idx & 2047;
    float gf = g_part[0][0 * 64 * KD + idx] + g_part[1][0 * 64 * KD + idx] + bf_[j];
    float gi = g_part[0][1 * 64 * KD + idx] + g_part[1][1 * 64 * KD + idx] + bi_[j];
    float gc = g_part[0][2 * 64 * KD + idx] + g_part[1][2 * 64 * KD + idx] + bc_[j];
    float go = g_part[0][3 * 64 * KD + idx] + g_part[1][3 * 64 * KD + idx] + bo_[j];
    float f  = 1.f / (1.f + expf(-gf));
    float ii = 1.f / (1.f + expf(-gi));
    float ct = tanhf(gc);
    float o  = 1.f / (1.f + expf(-go));
    float c  = f * c_prev[idx] + ii * ct;
    float h  = o * tanhf(c);
    out[r * NOUT + 2048 + j] = h;
    out[r * NOUT + 4096 + j] = c;
}

// ---------------------------------------------------------------------------
extern "C" void kernel_launch(void* const* d_in, const int* in_sizes, int n_in,
                              void* d_out, int out_size) {
    const float* x      = (const float*)d_in[0];
    const float* h_prev = (const float*)d_in[1];
    const float* c_prev = (const float*)d_in[2];
    const float* Wfh = (const float*)d_in[3];
    const float* Wfx = (const float*)d_in[4];
    const float* bf  = (const float*)d_in[5];
    const float* Wih = (const float*)d_in[6];
    const float* Wix = (const float*)d_in[7];
    const float* bi  = (const float*)d_in[8];
    const float* Woh = (const float*)d_in[9];
    const float* Wox = (const float*)d_in[10];
    const float* bo  = (const float*)d_in[11];
    const float* Wch = (const float*)d_in[12];
    const float* Wcx = (const float*)d_in[13];
    const float* bc  = (const float*)d_in[14];
    const float* Wy  = (const float*)d_in[15];
    const float* by  = (const float*)d_in[16];
    float* out = (float*)d_out;

    static int smem_set = 0;
    if (!smem_set) {
        cudaFuncSetAttribute(gemm_hmma, cudaFuncAttributeMaxDynamicSharedMemorySize,
                             SMEM_BYTES);
        smem_set = 1;
    }

    make_A<<<256, 256>>>(h_prev, x);
    gemm_hmma<<<288, 256, SMEM_BYTES>>>(Wfh, Wfx, Wih, Wix, Wch, Wcx, Woh, Wox,
                                        Wy, by, out);
    fuse_kernel<<<512, 256>>>(c_prev, bf, bi, bc, bo, out);
}

// round 13
// speedup vs baseline: 1.5779x; 1.0565x over previous
#include <cuda_runtime.h>
#include <cuda_fp16.h>
#include <cstdint>

// LSTM single step, B=64, H=I=O=2048.  out[64,6144] = concat(y, h_new, c_new).
// mma.sync fp16 (fp16 accum, fp32 dump once per k64 chunk; chain length 2).
// GEMM kernel: phase 0 converts concat(h,x)->fp16 g_A cooperatively, then a
// monotone-ticket grid barrier (288 CTAs all co-resident at 2/SM), then the
// r12-proven HMMA GEMM: 256 gate CTAs (split-K at h/x) + 32 y CTAs, 32 k64
// chunks, 8 warps = 2M x 2N x 2K (warp tile 32x32, k-halves merged via smem).
// Separate fuse kernel does partial-sum + biases + LSTM pointwise.

#define KD 2048
#define NOUT 6144
#define NCTA 288u

__device__ __half g_A[64 * 4096];            // concat(h, x) fp16
__device__ float g_part[2][4 * 64 * KD];     // split-K gate partials
__device__ unsigned g_tk0;                   // barrier ticket (monotone)

#define SWZ128(o) ((o) ^ (((o) >> 3) & 0x70))

__device__ __forceinline__ uint32_t smem_u32(const void* p) {
    uint32_t a;
    asm("{ .reg .u64 t; cvta.to.shared.u64 t, %1; cvt.u32.u64 %0, t; }"
        : "=r"(a) : "l"(p));
    return a;
}

#define LDSM4(r, addr)                                                       \
    asm volatile("ldmatrix.sync.aligned.m8n8.x4.shared.b16 {%0,%1,%2,%3}, [%4];" \
                 : "=r"((r)[0]), "=r"((r)[1]), "=r"((r)[2]), "=r"((r)[3])    \
                 : "r"(addr))
#define LDSM4T(r, addr)                                                      \
    asm volatile("ldmatrix.sync.aligned.m8n8.x4.trans.shared.b16 {%0,%1,%2,%3}, [%4];" \
                 : "=r"((r)[0]), "=r"((r)[1]), "=r"((r)[2]), "=r"((r)[3])    \
                 : "r"(addr))
#define MMA16816H(d, a, b0, b1)                                              \
    asm volatile("mma.sync.aligned.m16n8k16.row.col.f16.f16.f16.f16 "        \
                 "{%0,%1}, {%2,%3,%4,%5}, {%6,%7}, {%0,%1};"                 \
                 : "+r"((d)[0]), "+r"((d)[1])                                \
                 : "r"((a)[0]), "r"((a)[1]), "r"((a)[2]), "r"((a)[3]),       \
                   "r"(b0), "r"(b1))
#define CP_ASYNC16(saddr, gptr)                                              \
    asm volatile("cp.async.cg.shared.global [%0], [%1], 16;" :: "r"(saddr), "l"(gptr))
#define CP_COMMIT() asm volatile("cp.async.commit_group;" ::: "memory")
#define CP_WAIT1()  asm volatile("cp.async.wait_group 1;" ::: "memory")

// SMEM (relative to 1KB-aligned base):
//   A stages (3): s*8192           (64 rows x 128B fp16)
//   B stages (2): 24576 + s*8192
#define A_OFF(s)  ((uint32_t)(s) * 8192u)
#define B_OFF(s)  (24576u + (uint32_t)(s) * 8192u)
#define SMEM_BYTES (40960 + 1024)

// Grid barrier: all 288 CTAs are co-resident (2 CTAs/SM guaranteed by
// launch_bounds + smem), so spinning is deadlock-free.  Monotone ticket is
// correct across graph replays with no reset.
__device__ __forceinline__ void grid_barrier(unsigned* ctr) {
    __threadfence();
    __syncthreads();
    if (threadIdx.x == 0) {
        unsigned my = atomicAdd(ctr, 1u);
        unsigned target = (my / NCTA + 1u) * NCTA;
        while (*(volatile unsigned*)ctr < target) __nanosleep(64);
    }
    __syncthreads();
    __threadfence();
}

// ---------------------------------------------------------------------------
__global__ void __launch_bounds__(256, 2) gemm_hmma(
    const float* __restrict__ h_prev, const float* __restrict__ x_in,
    const float* __restrict__ Wfh, const float* __restrict__ Wfx,
    const float* __restrict__ Wih, const float* __restrict__ Wix,
    const float* __restrict__ Wch, const float* __restrict__ Wcx,
    const float* __restrict__ Woh, const float* __restrict__ Wox,
    const float* __restrict__ Wy,  const float* __restrict__ by_,
    float* __restrict__ out)
{
    extern __shared__ char smem_raw[];
    uint32_t su0 = smem_u32(smem_raw);
    const uint32_t su = (su0 + 1023u) & ~1023u;
    char* sm = smem_raw + (su - su0);

    const int t = threadIdx.x, bx = blockIdx.x;
    const int lane = t & 31, wid = t >> 5;
    const int kh = wid >> 2, mi = (wid >> 1) & 1, ni = wid & 1;
    const int lr = lane & 15, lc = lane >> 4;

    // ------------- phase 0: build g_A = fp16 concat(h, x) ------------------
    {
        int u = bx * 256 + t;                   // 73728 threads, 65536 units
        if (u < 65536) {
            int idx = u * 4;
            int r = idx >> 12, k = idx & 4095;
            const float* src = (k < 2048) ? (h_prev + r * 2048 + k)
                                          : (x_in + r * 2048 + (k - 2048));
            float4 v = *(const float4*)src;
            __half2 p0 = __floats2half2_rn(v.x, v.y);
            __half2 p1 = __floats2half2_rn(v.z, v.w);
            *(uint2*)(g_A + idx) = make_uint2(*(uint32_t*)&p0, *(uint32_t*)&p1);
        }
    }
    grid_barrier(&g_tk0);

    // ------------- phase 1: GEMM (r12 structure) ----------------------------
    const float* WH[4] = {Wfh, Wih, Wch, Woh};
    const float* WX[4] = {Wfx, Wix, Wcx, Wox};

    const bool isY = (bx >= 256);
    const float *W;
    float* Cout;
    int jj, ldc, aCol0;
    if (!isY) {
        const int tile = bx >> 1, kk = bx & 1;
        const int g = tile >> 5;
        jj = (tile & 31) * 64;
        W = kk ? WX[g] : WH[g];
        aCol0 = kk * 2048;
        Cout = g_part[kk] + g * 64 * KD + jj;
        ldc = KD;
    } else {
        jj = (bx - 256) * 64;
        W = Wy;
        aCol0 = 0;
        Cout = out + jj;
        ldc = NOUT;
    }

    const int brow = t >> 2, bseg = t & 3;      // B staging: 64 k-rows x 4 segs

    float master[2][4][4];
    uint32_t acch[2][4][2];
#pragma unroll
    for (int mf = 0; mf < 2; mf++)
#pragma unroll
        for (int j = 0; j < 4; j++) {
#pragma unroll
            for (int q = 0; q < 4; q++) master[mf][j][q] = 0.f;
            acch[mf][j][0] = 0u; acch[mf][j][1] = 0u;
        }

    auto issueA = [&](int c, int s) {
        const int aK = aCol0 + c * 64;
#pragma unroll
        for (int ui = 0; ui < 2; ui++) {
            const int u = t * 2 + ui;
            const int row = u >> 3, cs = u & 7;
            const uint32_t saddr = su + A_OFF(s) + SWZ128(row * 128 + cs * 16);
            const __half* gsrc = g_A + (size_t)row * 4096 + aK + cs * 8;
            CP_ASYNC16(saddr, gsrc);
        }
    };
    auto ldgB = [&](int c, float4* rb) {
        const float* src = W + (size_t)(c * 64 + brow) * 2048 + jj + bseg * 16;
        rb[0] = *(const float4*)(src + 0);
        rb[1] = *(const float4*)(src + 4);
        rb[2] = *(const float4*)(src + 8);
        rb[3] = *(const float4*)(src + 12);
    };

    issueA(0, 0);
    CP_COMMIT();
    float4 rb[4];
    ldgB(0, rb);

    for (int c = 0; c < 32; ++c) {
        const int s = c & 1;

        // Convert + STS B(c) fp32 -> fp16.  (Consumes rb.)
        {
            __half2 p[8];
            p[0] = __floats2half2_rn(rb[0].x, rb[0].y);
            p[1] = __floats2half2_rn(rb[0].z, rb[0].w);
            p[2] = __floats2half2_rn(rb[1].x, rb[1].y);
            p[3] = __floats2half2_rn(rb[1].z, rb[1].w);
            p[4] = __floats2half2_rn(rb[2].x, rb[2].y);
            p[5] = __floats2half2_rn(rb[2].z, rb[2].w);
            p[6] = __floats2half2_rn(rb[3].x, rb[3].y);
            p[7] = __floats2half2_rn(rb[3].z, rb[3].w);
            const uint32_t rbse = brow * 128 + bseg * 32;
            *(uint4*)(sm + B_OFF(s) + SWZ128(rbse)) =
                make_uint4(*(uint32_t*)&p[0], *(uint32_t*)&p[1],
                           *(uint32_t*)&p[2], *(uint32_t*)&p[3]);
            *(uint4*)(sm + B_OFF(s) + SWZ128(rbse + 16)) =
                make_uint4(*(uint32_t*)&p[4], *(uint32_t*)&p[5],
                           *(uint32_t*)&p[6], *(uint32_t*)&p[7]);
        }

        // Prefetches for chunk c+1, issued BEFORE the wait/barrier so the
        // B LDGs get maximal latency cover.
        if (c + 1 < 32) {
            issueA(c + 1, (c + 1) % 3);
            CP_COMMIT();
            ldgB(c + 1, rb);
        } else {
            CP_COMMIT();
        }
        CP_WAIT1();           // A(c) resident
        __syncthreads();

        // Compute chunk c, this warp's k32 half: 2 ks steps x 8 MMAs.
        {
            const int sa = c % 3;
            const uint32_t aBase = su + A_OFF(sa);
            const uint32_t bBase = su + B_OFF(s);
#pragma unroll
            for (int ksl = 0; ksl < 2; ksl++) {
                const int ks = kh * 2 + ksl;
                uint32_t a0[4], a1[4];
                LDSM4(a0, aBase + SWZ128((mi * 32 + lr) * 128 + ks * 32 + lc * 16));
                LDSM4(a1, aBase + SWZ128((mi * 32 + 16 + lr) * 128 + ks * 32 + lc * 16));
                const uint32_t brw = (ks * 16 + lr) * 128 + ni * 64;
                uint32_t b0[4], b1[4];
                LDSM4T(b0, bBase + SWZ128(brw + lc * 16));
                LDSM4T(b1, bBase + SWZ128(brw + 32 + lc * 16));
                MMA16816H(acch[0][0], a0, b0[0], b0[1]);
                MMA16816H(acch[0][1], a0, b0[2], b0[3]);
                MMA16816H(acch[0][2], a0, b1[0], b1[1]);
                MMA16816H(acch[0][3], a0, b1[2], b1[3]);
                MMA16816H(acch[1][0], a1, b0[0], b0[1]);
                MMA16816H(acch[1][1], a1, b0[2], b0[3]);
                MMA16816H(acch[1][2], a1, b1[0], b1[1]);
                MMA16816H(acch[1][3], a1, b1[2], b1[3]);
            }
            // dump chunk (chain of 2) into fp32 masters, re-zero
#pragma unroll
            for (int mf = 0; mf < 2; mf++)
#pragma unroll
                for (int j = 0; j < 4; j++) {
                    float2 lo = __half22float2(*(__half2*)&acch[mf][j][0]);
                    float2 hi = __half22float2(*(__half2*)&acch[mf][j][1]);
                    master[mf][j][0] += lo.x; master[mf][j][1] += lo.y;
                    master[mf][j][2] += hi.x; master[mf][j][3] += hi.y;
                    acch[mf][j][0] = 0u; acch[mf][j][1] = 0u;
                }
        }
    }

    // Epilogue: combine the two k-halves via smem, then write.
    __syncthreads();                       // A/B buffers now free
    float* ex = (float*)sm;                // 4 tiles x 32x33 fp32 (16.9 KB)
    const int tl = mi * 2 + ni;
    if (kh == 1) {
#pragma unroll
        for (int mf = 0; mf < 2; mf++) {
            const int mb = mf * 16 + (lane >> 2);
#pragma unroll
            for (int j = 0; j < 4; j++) {
                const int nb = j * 8 + (lane & 3) * 2;
                float* p = ex + tl * 1056 + mb * 33 + nb;
                p[0]          = master[mf][j][0];
                p[1]          = master[mf][j][1];
                p[8 * 33]     = master[mf][j][2];
                p[8 * 33 + 1] = master[mf][j][3];
            }
        }
    }
    __syncthreads();
    if (kh == 0) {
#pragma unroll
        for (int mf = 0; mf < 2; mf++) {
            const int mb = mf * 16 + (lane >> 2);
            const int m0 = mi * 32 + mb;
#pragma unroll
            for (int j = 0; j < 4; j++) {
                const int nb = j * 8 + (lane & 3) * 2;
                const int n = ni * 32 + nb;
                const float* p = ex + tl * 1056 + mb * 33 + nb;
                float b0 = 0.f, b1 = 0.f;
                if (isY) { b0 = by_[jj + n]; b1 = by_[jj + n + 1]; }
                *(float2*)(Cout + (size_t)m0 * ldc + n) = make_float2(
                    master[mf][j][0] + p[0] + b0,
                    master[mf][j][1] + p[1] + b1);
                *(float2*)(Cout + (size_t)(m0 + 8) * ldc + n) = make_float2(
                    master[mf][j][2] + p[8 * 33] + b0,
                    master[mf][j][3] + p[8 * 33 + 1] + b1);
            }
        }
    }
}

// ---------------------------------------------------------------------------
// Fuse: sum split-K partials + biases, LSTM pointwise, write h,c.
// ---------------------------------------------------------------------------
__global__ void fuse_kernel(const float* __restrict__ c_prev,
                            const float* __restrict__ bf_, const float* __restrict__ bi_,
                            const float* __restrict__ bc_, const float* __restrict__ bo_,
                            float* __restrict__ out) {
    int idx = blockIdx.x * 256 + threadIdx.x;   // 64 * 2048
    int r = idx >> 11, j = idx & 2047;
    float gf = g_part[0][0 * 64 * KD + idx] + g_part[1][0 * 64 * KD + idx] + bf_[j];
    float gi = g_part[0][1 * 64 * KD + idx] + g_part[1][1 * 64 * KD + idx] + bi_[j];
    float gc = g_part[0][2 * 64 * KD + idx] + g_part[1][2 * 64 * KD + idx] + bc_[j];
    float go = g_part[0][3 * 64 * KD + idx] + g_part[1][3 * 64 * KD + idx] + bo_[j];
    float f  = 1.f / (1.f + expf(-gf));
    float ii = 1.f / (1.f + expf(-gi));
    float ct = tanhf(gc);
    float o  = 1.f / (1.f + expf(-go));
    float c  = f * c_prev[idx] + ii * ct;
    float h  = o * tanhf(c);
    out[r * NOUT + 2048 + j] = h;
    out[r * NOUT + 4096 + j] = c;
}

// ---------------------------------------------------------------------------
extern "C" void kernel_launch(void* const* d_in, const int* in_sizes, int n_in,
                              void* d_out, int out_size) {
    const float* x      = (const float*)d_in[0];
    const float* h_prev = (const float*)d_in[1];
    const float* c_prev = (const float*)d_in[2];
    const float* Wfh = (const float*)d_in[3];
    const float* Wfx = (const float*)d_in[4];
    const float* bf  = (const float*)d_in[5];
    const float* Wih = (const float*)d_in[6];
    const float* Wix = (const float*)d_in[7];
    const float* bi  = (const float*)d_in[8];
    const float* Woh = (const float*)d_in[9];
    const float* Wox = (const float*)d_in[10];
    const float* bo  = (const float*)d_in[11];
    const float* Wch = (const float*)d_in[12];
    const float* Wcx = (const float*)d_in[13];
    const float* bc  = (const float*)d_in[14];
    const float* Wy  = (const float*)d_in[15];
    const float* by  = (const float*)d_in[16];
    float* out = (float*)d_out;

    static int smem_set = 0;
    if (!smem_set) {
        cudaFuncSetAttribute(gemm_hmma, cudaFuncAttributeMaxDynamicSharedMemorySize,
                             SMEM_BYTES);
        smem_set = 1;
    }

    gemm_hmma<<<288, 256, SMEM_BYTES>>>(h_prev, x,
                                        Wfh, Wfx, Wih, Wix, Wch, Wcx, Woh, Wox,
                                        Wy, by, out);
    fuse_kernel<<<512, 256>>>(c_prev, bf, bi, bc, bo, out);
}

// round 14
// speedup vs baseline: 1.6278x; 1.0316x over previous
#include <cuda_runtime.h>
#include <cuda_fp16.h>
#include <cstdint>

// LSTM single step, B=64, H=I=O=2048.  out[64,6144] = concat(y, h_new, c_new).
// ONE kernel, 288 CTAs (all co-resident at 2 CTAs/SM), 3 phases:
//   0: convert concat(h,x) -> fp16 g_A (cooperative)         ~1.5us
//   1: r12 HMMA GEMM (fp16 accum, fp32 dump per k64 chunk):
//      256 gate CTAs (split-K at h/x) + 32 y CTAs, 32 chunks,
//      8 warps = 2M x 2N x 2K, warp tile 32x32                ~39us
//   2: partial-sum + biases + LSTM pointwise -> h, c          ~2us
// Grid barriers: monotone-ticket atomics (replay-safe, deterministic).

#define KD 2048
#define NOUT 6144
#define NCTA 288u

__device__ __half g_A[64 * 4096];            // concat(h, x) fp16
__device__ float g_part[2][4 * 64 * KD];     // split-K gate partials
__device__ unsigned g_tk0, g_tk1;            // barrier tickets (monotone)

#define SWZ128(o) ((o) ^ (((o) >> 3) & 0x70))

__device__ __forceinline__ uint32_t smem_u32(const void* p) {
    uint32_t a;
    asm("{ .reg .u64 t; cvta.to.shared.u64 t, %1; cvt.u32.u64 %0, t; }"
        : "=r"(a) : "l"(p));
    return a;
}

#define LDSM4(r, addr)                                                       \
    asm volatile("ldmatrix.sync.aligned.m8n8.x4.shared.b16 {%0,%1,%2,%3}, [%4];" \
                 : "=r"((r)[0]), "=r"((r)[1]), "=r"((r)[2]), "=r"((r)[3])    \
                 : "r"(addr))
#define LDSM4T(r, addr)                                                      \
    asm volatile("ldmatrix.sync.aligned.m8n8.x4.trans.shared.b16 {%0,%1,%2,%3}, [%4];" \
                 : "=r"((r)[0]), "=r"((r)[1]), "=r"((r)[2]), "=r"((r)[3])    \
                 : "r"(addr))
#define MMA16816H(d, a, b0, b1)                                              \
    asm volatile("mma.sync.aligned.m16n8k16.row.col.f16.f16.f16.f16 "        \
                 "{%0,%1}, {%2,%3,%4,%5}, {%6,%7}, {%0,%1};"                 \
                 : "+r"((d)[0]), "+r"((d)[1])                                \
                 : "r"((a)[0]), "r"((a)[1]), "r"((a)[2]), "r"((a)[3]),       \
                   "r"(b0), "r"(b1))
#define CP_ASYNC16(saddr, gptr)                                              \
    asm volatile("cp.async.cg.shared.global [%0], [%1], 16;" :: "r"(saddr), "l"(gptr))
#define CP_COMMIT() asm volatile("cp.async.commit_group;" ::: "memory")
#define CP_WAIT1()  asm volatile("cp.async.wait_group 1;" ::: "memory")

// SMEM (relative to 1KB-aligned base):
//   A stages (3): s*8192           (64 rows x 128B fp16)
//   B stages (2): 24576 + s*8192
#define A_OFF(s)  ((uint32_t)(s) * 8192u)
#define B_OFF(s)  (24576u + (uint32_t)(s) * 8192u)
#define SMEM_BYTES (40960 + 1024)

// Grid barrier: all 288 CTAs co-resident (2/SM by launch_bounds + smem), so
// spinning is deadlock-free.  Monotone ticket => replay-safe, no reset.
__device__ __forceinline__ void grid_barrier(unsigned* ctr) {
    __threadfence();
    __syncthreads();
    if (threadIdx.x == 0) {
        unsigned my = atomicAdd(ctr, 1u);
        unsigned target = (my / NCTA + 1u) * NCTA;
        while (*(volatile unsigned*)ctr < target) __nanosleep(64);
    }
    __syncthreads();
    __threadfence();
}

// ---------------------------------------------------------------------------
__global__ void __launch_bounds__(256, 2) lstm_fused(
    const float* __restrict__ h_prev, const float* __restrict__ x_in,
    const float* __restrict__ c_prev,
    const float* __restrict__ Wfh, const float* __restrict__ Wfx,
    const float* __restrict__ Wih, const float* __restrict__ Wix,
    const float* __restrict__ Wch, const float* __restrict__ Wcx,
    const float* __restrict__ Woh, const float* __restrict__ Wox,
    const float* __restrict__ Wy,
    const float* __restrict__ bf_, const float* __restrict__ bi_,
    const float* __restrict__ bc_, const float* __restrict__ bo_,
    const float* __restrict__ by_,
    float* __restrict__ out)
{
    extern __shared__ char smem_raw[];
    uint32_t su0 = smem_u32(smem_raw);
    const uint32_t su = (su0 + 1023u) & ~1023u;
    char* sm = smem_raw + (su - su0);

    const int t = threadIdx.x, bx = blockIdx.x;
    const int lane = t & 31, wid = t >> 5;
    const int kh = wid >> 2, mi = (wid >> 1) & 1, ni = wid & 1;
    const int lr = lane & 15, lc = lane >> 4;

    // ------------- phase 0: build g_A = fp16 concat(h, x) ------------------
    {
        int u = bx * 256 + t;                   // 73728 threads, 65536 units
        if (u < 65536) {
            int idx = u * 4;
            int r = idx >> 12, k = idx & 4095;
            const float* src = (k < 2048) ? (h_prev + r * 2048 + k)
                                          : (x_in + r * 2048 + (k - 2048));
            float4 v = *(const float4*)src;
            __half2 p0 = __floats2half2_rn(v.x, v.y);
            __half2 p1 = __floats2half2_rn(v.z, v.w);
            *(uint2*)(g_A + idx) = make_uint2(*(uint32_t*)&p0, *(uint32_t*)&p1);
        }
    }
    grid_barrier(&g_tk0);

    // ------------- phase 1: GEMM (r12 structure) ---------------------------
    const float* WH[4] = {Wfh, Wih, Wch, Woh};
    const float* WX[4] = {Wfx, Wix, Wcx, Wox};

    const bool isY = (bx >= 256);
    const float *W;
    float* Cout;
    int jj, ldc, aCol0;
    if (!isY) {
        const int tile = bx >> 1, kk = bx & 1;
        const int g = tile >> 5;
        jj = (tile & 31) * 64;
        W = kk ? WX[g] : WH[g];
        aCol0 = kk * 2048;
        Cout = g_part[kk] + g * 64 * KD + jj;
        ldc = KD;
    } else {
        jj = (bx - 256) * 64;
        W = Wy;
        aCol0 = 0;
        Cout = out + jj;
        ldc = NOUT;
    }

    const int brow = t >> 2, bseg = t & 3;      // B staging: 64 k-rows x 4 segs

    float master[2][4][4];
    uint32_t acch[2][4][2];
#pragma unroll
    for (int mf = 0; mf < 2; mf++)
#pragma unroll
        for (int j = 0; j < 4; j++) {
#pragma unroll
            for (int q = 0; q < 4; q++) master[mf][j][q] = 0.f;
            acch[mf][j][0] = 0u; acch[mf][j][1] = 0u;
        }

    auto issueA = [&](int c, int s) {
        const int aK = aCol0 + c * 64;
#pragma unroll
        for (int ui = 0; ui < 2; ui++) {
            const int u = t * 2 + ui;
            const int row = u >> 3, cs = u & 7;
            const uint32_t saddr = su + A_OFF(s) + SWZ128(row * 128 + cs * 16);
            const __half* gsrc = g_A + (size_t)row * 4096 + aK + cs * 8;
            CP_ASYNC16(saddr, gsrc);
        }
    };
    auto ldgB = [&](int c, float4* rb) {
        const float* src = W + (size_t)(c * 64 + brow) * 2048 + jj + bseg * 16;
        rb[0] = *(const float4*)(src + 0);
        rb[1] = *(const float4*)(src + 4);
        rb[2] = *(const float4*)(src + 8);
        rb[3] = *(const float4*)(src + 12);
    };

    issueA(0, 0);
    CP_COMMIT();
    float4 rb[4];
    ldgB(0, rb);

    for (int c = 0; c < 32; ++c) {
        const int s = c & 1;

        // Convert + STS B(c) fp32 -> fp16.  (Consumes rb.)
        {
            __half2 p[8];
            p[0] = __floats2half2_rn(rb[0].x, rb[0].y);
            p[1] = __floats2half2_rn(rb[0].z, rb[0].w);
            p[2] = __floats2half2_rn(rb[1].x, rb[1].y);
            p[3] = __floats2half2_rn(rb[1].z, rb[1].w);
            p[4] = __floats2half2_rn(rb[2].x, rb[2].y);
            p[5] = __floats2half2_rn(rb[2].z, rb[2].w);
            p[6] = __floats2half2_rn(rb[3].x, rb[3].y);
            p[7] = __floats2half2_rn(rb[3].z, rb[3].w);
            const uint32_t rbse = brow * 128 + bseg * 32;
            *(uint4*)(sm + B_OFF(s) + SWZ128(rbse)) =
                make_uint4(*(uint32_t*)&p[0], *(uint32_t*)&p[1],
                           *(uint32_t*)&p[2], *(uint32_t*)&p[3]);
            *(uint4*)(sm + B_OFF(s) + SWZ128(rbse + 16)) =
                make_uint4(*(uint32_t*)&p[4], *(uint32_t*)&p[5],
                           *(uint32_t*)&p[6], *(uint32_t*)&p[7]);
        }

        // Prefetch chunk c+1 BEFORE the wait/barrier for max latency cover.
        if (c + 1 < 32) {
            issueA(c + 1, (c + 1) % 3);
            CP_COMMIT();
            ldgB(c + 1, rb);
        } else {
            CP_COMMIT();
        }
        CP_WAIT1();           // A(c) resident
        __syncthreads();

        // Compute chunk c, this warp's k32 half: 2 ks steps x 8 MMAs.
        {
            const int sa = c % 3;
            const uint32_t aBase = su + A_OFF(sa);
            const uint32_t bBase = su + B_OFF(s);
#pragma unroll
            for (int ksl = 0; ksl < 2; ksl++) {
                const int ks = kh * 2 + ksl;
                uint32_t a0[4], a1[4];
                LDSM4(a0, aBase + SWZ128((mi * 32 + lr) * 128 + ks * 32 + lc * 16));
                LDSM4(a1, aBase + SWZ128((mi * 32 + 16 + lr) * 128 + ks * 32 + lc * 16));
                const uint32_t brw = (ks * 16 + lr) * 128 + ni * 64;
                uint32_t b0[4], b1[4];
                LDSM4T(b0, bBase + SWZ128(brw + lc * 16));
                LDSM4T(b1, bBase + SWZ128(brw + 32 + lc * 16));
                MMA16816H(acch[0][0], a0, b0[0], b0[1]);
                MMA16816H(acch[0][1], a0, b0[2], b0[3]);
                MMA16816H(acch[0][2], a0, b1[0], b1[1]);
                MMA16816H(acch[0][3], a0, b1[2], b1[3]);
                MMA16816H(acch[1][0], a1, b0[0], b0[1]);
                MMA16816H(acch[1][1], a1, b0[2], b0[3]);
                MMA16816H(acch[1][2], a1, b1[0], b1[1]);
                MMA16816H(acch[1][3], a1, b1[2], b1[3]);
            }
            // dump chunk (chain of 2) into fp32 masters, re-zero
#pragma unroll
            for (int mf = 0; mf < 2; mf++)
#pragma unroll
                for (int j = 0; j < 4; j++) {
                    float2 lo = __half22float2(*(__half2*)&acch[mf][j][0]);
                    float2 hi = __half22float2(*(__half2*)&acch[mf][j][1]);
                    master[mf][j][0] += lo.x; master[mf][j][1] += lo.y;
                    master[mf][j][2] += hi.x; master[mf][j][3] += hi.y;
                    acch[mf][j][0] = 0u; acch[mf][j][1] = 0u;
                }
        }
    }

    // GEMM epilogue: combine the two k-halves via smem, then write.
    __syncthreads();                       // A/B buffers now free
    float* ex = (float*)sm;                // 4 tiles x 32x33 fp32 (16.9 KB)
    const int tl = mi * 2 + ni;
    if (kh == 1) {
#pragma unroll
        for (int mf = 0; mf < 2; mf++) {
            const int mb = mf * 16 + (lane >> 2);
#pragma unroll
            for (int j = 0; j < 4; j++) {
                const int nb = j * 8 + (lane & 3) * 2;
                float* p = ex + tl * 1056 + mb * 33 + nb;
                p[0]          = master[mf][j][0];
                p[1]          = master[mf][j][1];
                p[8 * 33]     = master[mf][j][2];
                p[8 * 33 + 1] = master[mf][j][3];
            }
        }
    }
    __syncthreads();
    if (kh == 0) {
#pragma unroll
        for (int mf = 0; mf < 2; mf++) {
            const int mb = mf * 16 + (lane >> 2);
            const int m0 = mi * 32 + mb;
#pragma unroll
            for (int j = 0; j < 4; j++) {
                const int nb = j * 8 + (lane & 3) * 2;
                const int n = ni * 32 + nb;
                const float* p = ex + tl * 1056 + mb * 33 + nb;
                float b0 = 0.f, b1 = 0.f;
                if (isY) { b0 = by_[jj + n]; b1 = by_[jj + n + 1]; }
                *(float2*)(Cout + (size_t)m0 * ldc + n) = make_float2(
                    master[mf][j][0] + p[0] + b0,
                    master[mf][j][1] + p[1] + b1);
                *(float2*)(Cout + (size_t)(m0 + 8) * ldc + n) = make_float2(
                    master[mf][j][2] + p[8 * 33] + b0,
                    master[mf][j][3] + p[8 * 33 + 1] + b1);
            }
        }
    }

    grid_barrier(&g_tk1);

    // ------------- phase 2: pointwise LSTM (partials L2-hot) ---------------
    {
        int u = bx * 256 + t;                   // 65536 float2 units
        if (u < 65536) {
            const int idx = u * 2;
            const int r = idx >> 11, j = idx & 2047;
            float2 gf = *(const float2*)&g_part[0][0 * 64 * KD + idx];
            float2 gi = *(const float2*)&g_part[0][1 * 64 * KD + idx];
            float2 gc = *(const float2*)&g_part[0][2 * 64 * KD + idx];
            float2 go = *(const float2*)&g_part[0][3 * 64 * KD + idx];
            float2 q;
            q = *(const float2*)&g_part[1][0 * 64 * KD + idx]; gf.x += q.x; gf.y += q.y;
            q = *(const float2*)&g_part[1][1 * 64 * KD + idx]; gi.x += q.x; gi.y += q.y;
            q = *(const float2*)&g_part[1][2 * 64 * KD + idx]; gc.x += q.x; gc.y += q.y;
            q = *(const float2*)&g_part[1][3 * 64 * KD + idx]; go.x += q.x; go.y += q.y;
            float2 vbf = *(const float2*)(bf_ + j);
            float2 vbi = *(const float2*)(bi_ + j);
            float2 vbc = *(const float2*)(bc_ + j);
            float2 vbo = *(const float2*)(bo_ + j);
            float2 cp  = *(const float2*)(c_prev + idx);
            float ga[2] = {gf.x + vbf.x, gf.y + vbf.y};
            float gb[2] = {gi.x + vbi.x, gi.y + vbi.y};
            float gg[2] = {gc.x + vbc.x, gc.y + vbc.y};
            float gd[2] = {go.x + vbo.x, go.y + vbo.y};
            float cpa[2] = {cp.x, cp.y};
            float hh[2], cc[2];
#pragma unroll
            for (int e = 0; e < 2; e++) {
                float f  = 1.f / (1.f + expf(-ga[e]));
                float ii = 1.f / (1.f + expf(-gb[e]));
                float ct = tanhf(gg[e]);
                float o  = 1.f / (1.f + expf(-gd[e]));
                cc[e] = f * cpa[e] + ii * ct;
                hh[e] = o * tanhf(cc[e]);
            }
            *(float2*)(out + r * NOUT + 2048 + j) = make_float2(hh[0], hh[1]);
            *(float2*)(out + r * NOUT + 4096 + j) = make_float2(cc[0], cc[1]);
        }
    }
}

// ---------------------------------------------------------------------------
extern "C" void kernel_launch(void* const* d_in, const int* in_sizes, int n_in,
                              void* d_out, int out_size) {
    const float* x      = (const float*)d_in[0];
    const float* h_prev = (const float*)d_in[1];
    const float* c_prev = (const float*)d_in[2];
    const float* Wfh = (const float*)d_in[3];
    const float* Wfx = (const float*)d_in[4];
    const float* bf  = (const float*)d_in[5];
    const float* Wih = (const float*)d_in[6];
    const float* Wix = (const float*)d_in[7];
    const float* bi  = (const float*)d_in[8];
    const float* Woh = (const float*)d_in[9];
    const float* Wox = (const float*)d_in[10];
    const float* bo  = (const float*)d_in[11];
    const float* Wch = (const float*)d_in[12];
    const float* Wcx = (const float*)d_in[13];
    const float* bc  = (const float*)d_in[14];
    const float* Wy  = (const float*)d_in[15];
    const float* by  = (const float*)d_in[16];
    float* out = (float*)d_out;

    static int smem_set = 0;
    if (!smem_set) {
        cudaFuncSetAttribute(lstm_fused, cudaFuncAttributeMaxDynamicSharedMemorySize,
                             SMEM_BYTES);
        smem_set = 1;
    }

    lstm_fused<<<288, 256, SMEM_BYTES>>>(h_prev, x, c_prev,
                                         Wfh, Wfx, Wih, Wix, Wch, Wcx, Woh, Wox,
                                         Wy, bf, bi, bc, bo, by, out);
}